// round 17
// baseline (speedup 1.0000x reference)
#include <cuda_runtime.h>
#include <cuda_bf16.h>
#include <cstdint>
#include <cstddef>

// Problem constants (static per reference)
#define NB  8
#define LQn 2048
#define CC  256
#define MH  8
#define LLv 4
#define DHd 32
#define SSt 3840
#define MLP 128   // M*L*P
#define KK  256   // GEMM K (= C)
#define NC  256   // GEMM N (all GEMMs are Nc=256 after fusion)

#define ASTR 40               // smem row stride in bf16 (80 B; conflict-free)
#define A_TILE_B (128 * 80)   // 10240 B : 128x32 bf16 tile
#define B_TILE_B (64 * 80)    //  5120 B :  64x32 bf16 tile
#define STAGE_B  (2 * A_TILE_B + 2 * B_TILE_B)   // 30720 B per stage

// ---------------- scratch (__device__ globals; allocation-free rule) -------
__device__ float g_value [(size_t)NB * SSt * CC];   // value (N,S,M,DH) fp32
__device__ float g_logits[(size_t)NB * LQn * 256];  // [off(128) | attn(128)]
__device__ float g_loc2  [(size_t)NB * LQn * MLP];  // fallback outputs
__device__ float g_att2  [(size_t)NB * LQn * MLP];
__device__ float g_bcat  [256];

// bf16 hi/lo split activations (A matrices, row-major [R][256])
__device__ __nv_bfloat16 g_aih[(size_t)NB * SSt * KK];
__device__ __nv_bfloat16 g_ail[(size_t)NB * SSt * KK];
__device__ __nv_bfloat16 g_aqh[(size_t)NB * LQn * KK];
__device__ __nv_bfloat16 g_aql[(size_t)NB * LQn * KK];
__device__ __nv_bfloat16 g_ath[(size_t)NB * LQn * KK];
__device__ __nv_bfloat16 g_atl[(size_t)NB * LQn * KK];
// bf16 hi/lo transposed weights (B matrices, [Nc][256] K-major)
__device__ __nv_bfloat16 g_bvh[256 * KK], g_bvl[256 * KK];  // W_val^T
__device__ __nv_bfloat16 g_bch[256 * KK], g_bcl[256 * KK];  // [W_off|W_attn]^T
__device__ __nv_bfloat16 g_boh[256 * KK], g_bol[256 * KK];  // W_out^T

__device__ __forceinline__ uint32_t smem_u32(const void* p) {
    uint32_t a;
    asm("{ .reg .u64 t; cvta.to.shared.u64 t, %1; cvt.u32.u64 %0, t; }"
        : "=r"(a) : "l"(p));
    return a;
}

// ---------------------------------------------------------------------------
// mma.sync GEMM, dual-matrix dispatch. CTA tile 128x64, 8 warps (32x32 each),
// BK=32, 2-stage cp.async, 2 CTAs/SM. 3-term bf16 split, fp32 accumulate.
// ---------------------------------------------------------------------------
__global__ __launch_bounds__(256, 2)
void gemm_mma2_kernel(
    const __nv_bfloat16* __restrict__ Ah0, const __nv_bfloat16* __restrict__ Al0,
    const __nv_bfloat16* __restrict__ Bh0, const __nv_bfloat16* __restrict__ Bl0,
    const float* __restrict__ bias0, float* __restrict__ C0,
    const __nv_bfloat16* __restrict__ Ah1, const __nv_bfloat16* __restrict__ Al1,
    const __nv_bfloat16* __restrict__ Bh1, const __nv_bfloat16* __restrict__ Bl1,
    const float* __restrict__ bias1, float* __restrict__ C1,
    int split)
{
    extern __shared__ __align__(128) char smem[];
    uint32_t sb = smem_u32(smem);
    int tid  = threadIdx.x;
    int lane = tid & 31;
    int wid  = tid >> 5;
    int wr   = wid >> 1;     // 0..3  (m warp row, 32 rows each)
    int wc   = wid & 1;      // 0..1  (n warp col, 32 cols each)

    int bid = blockIdx.x;
    const __nv_bfloat16 *Ah, *Al, *Bh, *Bl;
    const float* bias;
    float* Cmat;
    int local;
    if (bid < split) {
        Ah = Ah0; Al = Al0; Bh = Bh0; Bl = Bl0; bias = bias0; Cmat = C0;
        local = bid;
    } else {
        Ah = Ah1; Al = Al1; Bh = Bh1; Bl = Bl1; bias = bias1; Cmat = C1;
        local = bid - split;
    }
    int bm = (local >> 2) * 128;     // 4 col-tiles of 64 over Nc=256
    int bn = (local & 3) * 64;

    // staging maps
    int arow = tid >> 1;             // 0..127
    int aoff = (tid & 1) * 32;       // byte offset within 64B row data
    int brow = (tid & 127) >> 1;     // 0..63
    const __nv_bfloat16* gBsel = (tid >= 128 ? Bl : Bh) + (size_t)bn * KK;
    uint32_t bDstOff = 2 * A_TILE_B + (tid >= 128 ? B_TILE_B : 0);

    const __nv_bfloat16* gAh = Ah + (size_t)bm * KK;
    const __nv_bfloat16* gAl = Al + (size_t)bm * KK;

    float acc[2][4][4];
    #pragma unroll
    for (int i = 0; i < 2; i++)
        #pragma unroll
        for (int j = 0; j < 4; j++)
            #pragma unroll
            for (int r = 0; r < 4; r++) acc[i][j][r] = 0.f;

    int a_r = lane & 15;
    int a_k = (lane >> 4) << 3;
    int b_r = lane & 7;
    int b_k = ((lane >> 3) & 1) << 3;

    #define STAGE_LOAD(s, k0) do {                                              \
        uint32_t base = sb + (uint32_t)(s) * STAGE_B;                           \
        uint32_t ad = base + (uint32_t)arow * 80 + aoff;                        \
        const char* ga = (const char*)(gAh + (size_t)arow * KK + (k0)) + aoff;  \
        asm volatile("cp.async.cg.shared.global [%0], [%1], 16;"                \
                     :: "r"(ad), "l"(ga));                                      \
        asm volatile("cp.async.cg.shared.global [%0], [%1], 16;"                \
                     :: "r"(ad + 16), "l"(ga + 16));                            \
        uint32_t ad2 = ad + A_TILE_B;                                           \
        const char* gl = (const char*)(gAl + (size_t)arow * KK + (k0)) + aoff;  \
        asm volatile("cp.async.cg.shared.global [%0], [%1], 16;"                \
                     :: "r"(ad2), "l"(gl));                                     \
        asm volatile("cp.async.cg.shared.global [%0], [%1], 16;"                \
                     :: "r"(ad2 + 16), "l"(gl + 16));                           \
        uint32_t bd = base + bDstOff + (uint32_t)brow * 80 + aoff;              \
        const char* gb = (const char*)(gBsel + (size_t)brow * KK + (k0)) + aoff;\
        asm volatile("cp.async.cg.shared.global [%0], [%1], 16;"                \
                     :: "r"(bd), "l"(gb));                                      \
        asm volatile("cp.async.cg.shared.global [%0], [%1], 16;"                \
                     :: "r"(bd + 16), "l"(gb + 16));                            \
        asm volatile("cp.async.commit_group;" ::: "memory");                    \
    } while (0)

    STAGE_LOAD(0, 0);

    for (int kt = 0; kt < 8; kt++) {
        if (kt < 7) {
            STAGE_LOAD((kt + 1) & 1, (kt + 1) * 32);
            asm volatile("cp.async.wait_group 1;" ::: "memory");
        } else {
            asm volatile("cp.async.wait_group 0;" ::: "memory");
        }
        __syncthreads();

        uint32_t base = sb + (uint32_t)(kt & 1) * STAGE_B;
        uint32_t sAh = base;
        uint32_t sAl = base + A_TILE_B;
        uint32_t sBh = base + 2 * A_TILE_B;
        uint32_t sBl = sBh + B_TILE_B;

        #pragma unroll
        for (int kk = 0; kk < 32; kk += 16) {
            uint32_t ah[2][4], al[2][4], bh[4][2], bl[4][2];
            #pragma unroll
            for (int mi = 0; mi < 2; mi++) {
                int row = wr * 32 + mi * 16 + a_r;
                uint32_t off = (uint32_t)(row * ASTR + kk + a_k) * 2;
                asm volatile(
                    "ldmatrix.sync.aligned.m8n8.x4.shared.b16 {%0,%1,%2,%3}, [%4];"
                    : "=r"(ah[mi][0]), "=r"(ah[mi][1]), "=r"(ah[mi][2]), "=r"(ah[mi][3])
                    : "r"(sAh + off));
                asm volatile(
                    "ldmatrix.sync.aligned.m8n8.x4.shared.b16 {%0,%1,%2,%3}, [%4];"
                    : "=r"(al[mi][0]), "=r"(al[mi][1]), "=r"(al[mi][2]), "=r"(al[mi][3])
                    : "r"(sAl + off));
            }
            #pragma unroll
            for (int ni = 0; ni < 4; ni++) {
                int row = wc * 32 + ni * 8 + b_r;
                uint32_t off = (uint32_t)(row * ASTR + kk + b_k) * 2;
                asm volatile(
                    "ldmatrix.sync.aligned.m8n8.x2.shared.b16 {%0,%1}, [%2];"
                    : "=r"(bh[ni][0]), "=r"(bh[ni][1]) : "r"(sBh + off));
                asm volatile(
                    "ldmatrix.sync.aligned.m8n8.x2.shared.b16 {%0,%1}, [%2];"
                    : "=r"(bl[ni][0]), "=r"(bl[ni][1]) : "r"(sBl + off));
            }

            #define MMA(ACC, A, B)                                              \
                asm volatile(                                                   \
                    "mma.sync.aligned.m16n8k16.row.col.f32.bf16.bf16.f32 "      \
                    "{%0,%1,%2,%3}, {%4,%5,%6,%7}, {%8,%9}, {%0,%1,%2,%3};"     \
                    : "+f"((ACC)[0]), "+f"((ACC)[1]), "+f"((ACC)[2]), "+f"((ACC)[3]) \
                    : "r"((A)[0]), "r"((A)[1]), "r"((A)[2]), "r"((A)[3]),       \
                      "r"((B)[0]), "r"((B)[1]))

            #pragma unroll
            for (int mi = 0; mi < 2; mi++)
                #pragma unroll
                for (int ni = 0; ni < 4; ni++) {
                    MMA(acc[mi][ni], ah[mi], bh[ni]);   // Ah*Bh
                    MMA(acc[mi][ni], al[mi], bh[ni]);   // Al*Bh
                    MMA(acc[mi][ni], ah[mi], bl[ni]);   // Ah*Bl
                }
            #undef MMA
        }
        __syncthreads();
    }
    #undef STAGE_LOAD

    // ---- epilogue: fp32 + bias ----
    int r0 = bm + wr * 32;
    int c0 = bn + wc * 32;
    #pragma unroll
    for (int mi = 0; mi < 2; mi++) {
        int row = r0 + mi * 16 + (lane >> 2);
        #pragma unroll
        for (int ni = 0; ni < 4; ni++) {
            int col = c0 + ni * 8 + (lane & 3) * 2;
            float2 bv = *(const float2*)(bias + col);
            float2 v0 = {acc[mi][ni][0] + bv.x, acc[mi][ni][1] + bv.y};
            float2 v1 = {acc[mi][ni][2] + bv.x, acc[mi][ni][3] + bv.y};
            *(float2*)(Cmat + (size_t)row * NC + col)       = v0;
            *(float2*)(Cmat + (size_t)(row + 8) * NC + col) = v1;
        }
    }
}

// ---------------------------------------------------------------------------
// Combined prep + activation conversion (one launch).
// ---------------------------------------------------------------------------
#define PREP_ITEMS (3 * 65536 + 256)
#define PREP_BLKS  ((PREP_ITEMS + 255) / 256)

__global__ __launch_bounds__(256) void prepconv_kernel(
    const float* __restrict__ W_val, const float* __restrict__ W_off,
    const float* __restrict__ W_attn, const float* __restrict__ W_out,
    const float* __restrict__ b_off, const float* __restrict__ b_attn,
    __nv_bfloat16* __restrict__ bvh, __nv_bfloat16* __restrict__ bvl,
    __nv_bfloat16* __restrict__ bch, __nv_bfloat16* __restrict__ bcl,
    __nv_bfloat16* __restrict__ boh, __nv_bfloat16* __restrict__ bol,
    float* __restrict__ bcat,
    const float* __restrict__ s0, __nv_bfloat16* __restrict__ h0,
    __nv_bfloat16* __restrict__ l0, int n40,
    const float* __restrict__ s1, __nv_bfloat16* __restrict__ h1,
    __nv_bfloat16* __restrict__ l1, int n41)
{
    if (blockIdx.x < PREP_BLKS) {
        int gid = blockIdx.x * 256 + threadIdx.x;
        if (gid >= 3 * 65536) {
            int i = gid - 3 * 65536;
            if (i < 256) bcat[i] = (i < 128) ? b_off[i] : b_attn[i - 128];
            return;
        }
        int which = gid >> 16;
        int idx   = gid & 65535;
        int n = idx >> 8, k = idx & 255;
        float v;
        __nv_bfloat16 *dh, *dl;
        if (which == 0) {
            v = W_val[(size_t)k * 256 + n]; dh = bvh; dl = bvl;
        } else if (which == 1) {
            v = (n < 128) ? W_off[(size_t)k * 128 + n]
                          : W_attn[(size_t)k * 128 + (n - 128)];
            dh = bch; dl = bcl;
        } else {
            v = W_out[(size_t)k * 256 + n]; dh = boh; dl = bol;
        }
        __nv_bfloat16 h = __float2bfloat16(v);
        dh[idx] = h;
        dl[idx] = __float2bfloat16(v - __bfloat162float(h));
        return;
    }

    int i = (blockIdx.x - PREP_BLKS) * 256 + threadIdx.x;
    const float* s; __nv_bfloat16 *H8, *L8; int j;
    if (i < n40) { s = s0; H8 = h0; L8 = l0; j = i; }
    else {
        j = i - n40;
        if (j >= n41) return;
        s = s1; H8 = h1; L8 = l1;
    }
    float4 v = ((const float4*)s)[j];
    __nv_bfloat16 a0 = __float2bfloat16(v.x), a1 = __float2bfloat16(v.y);
    __nv_bfloat16 a2 = __float2bfloat16(v.z), a3 = __float2bfloat16(v.w);
    __nv_bfloat16 c0 = __float2bfloat16(v.x - __bfloat162float(a0));
    __nv_bfloat16 c1 = __float2bfloat16(v.y - __bfloat162float(a1));
    __nv_bfloat16 c2 = __float2bfloat16(v.z - __bfloat162float(a2));
    __nv_bfloat16 c3 = __float2bfloat16(v.w - __bfloat162float(a3));
    __nv_bfloat162* H = (__nv_bfloat162*)H8;
    __nv_bfloat162* L = (__nv_bfloat162*)L8;
    H[2 * j]     = __nv_bfloat162(a0, a1);
    H[2 * j + 1] = __nv_bfloat162(a2, a3);
    L[2 * j]     = __nv_bfloat162(c0, c1);
    L[2 * j + 1] = __nv_bfloat162(c2, c3);
}

// ---------------------------------------------------------------------------
// Fused postproc + sampling (validated round-13/15 version, unchanged).
// ---------------------------------------------------------------------------
__global__ __launch_bounds__(256) void sample_fused_kernel(
    const float* __restrict__ refpts, const float* __restrict__ logits,
    float* __restrict__ loc_out, float* __restrict__ attn_out,
    __nv_bfloat16* __restrict__ outh, __nv_bfloat16* __restrict__ outl)
{
    int gwarp = blockIdx.x * 8 + (threadIdx.x >> 5);   // (n,q,m), < 131072
    int lane  = threadIdx.x & 31;
    int m  = gwarp & 7;
    int nq = gwarp >> 3;
    int n  = nq >> 11;                 // / LQn

    int li = lane & 15;
    const float* lrow = logits + nq * 256 + m * 16;
    float offv = lrow[li];
    float lgv  = lrow[128 + li];
    float mx = lgv;
    #pragma unroll
    for (int d = 1; d < 16; d <<= 1)
        mx = fmaxf(mx, __shfl_xor_sync(0xffffffffu, mx, d));
    float ev = __expf(lgv - mx);
    float sum = ev;
    #pragma unroll
    for (int d = 1; d < 16; d <<= 1)
        sum += __shfl_xor_sync(0xffffffffu, sum, d);
    float attnv = ev / sum;

    const float innorm[4] = {1.f / 2048.f, 1.f / 1024.f, 1.f / 512.f, 1.f / 256.f};
    int lv = li >> 2;
    float rn = refpts[nq * 4 + lv];
    float locv = rn + offv * innorm[lv];

    if (lane < 16) {
        loc_out [gwarp * 16 + lane] = locv;
        attn_out[gwarp * 16 + lane] = attnv;
    }

    const int lens[4]   = {2048, 1024, 512, 256};
    const int starts[4] = {0, 2048, 3072, 3584};
    int T = lens[lv], st = starts[lv];
    float pos = locv * (float)T - 0.5f;
    float x0f = floorf(pos);
    float frac = pos - x0f;
    int x0 = (int)x0f;
    float w0 = (x0 >= 0 && x0 < T)         ? (1.f - frac) : 0.f;
    float w1 = (x0 + 1 >= 0 && x0 + 1 < T) ? frac         : 0.f;
    float aw0 = attnv * w0;
    float aw1 = attnv * w1;
    int i0 = min(max(x0, 0), T - 1) + st;
    int i1 = min(max(x0 + 1, 0), T - 1) + st;
    int packed = i0 | (i1 << 16);

    int grp = lane >> 3;                // 0..3 (point group)
    int c4  = (lane & 7) << 2;          // channel base 0,4,...,28
    const float* vbase = g_value + (n * SSt * CC + m * DHd + c4);
    float4 acc4 = {0.f, 0.f, 0.f, 0.f};
    #pragma unroll
    for (int t = 0; t < 4; t++) {
        int src = t * 4 + grp;
        float a0 = __shfl_sync(0xffffffffu, aw0, src);
        float a1 = __shfl_sync(0xffffffffu, aw1, src);
        int   pk = __shfl_sync(0xffffffffu, packed, src);
        int o0 = (pk & 0xFFFF) << 8;
        int o1 = ((unsigned)pk >> 16) << 8;
        float4 v0 = *(const float4*)(vbase + o0);
        float4 v1 = *(const float4*)(vbase + o1);
        acc4.x += a0 * v0.x + a1 * v1.x;
        acc4.y += a0 * v0.y + a1 * v1.y;
        acc4.z += a0 * v0.z + a1 * v1.z;
        acc4.w += a0 * v0.w + a1 * v1.w;
    }
    #pragma unroll
    for (int d = 8; d <= 16; d <<= 1) {
        acc4.x += __shfl_xor_sync(0xffffffffu, acc4.x, d);
        acc4.y += __shfl_xor_sync(0xffffffffu, acc4.y, d);
        acc4.z += __shfl_xor_sync(0xffffffffu, acc4.z, d);
        acc4.w += __shfl_xor_sync(0xffffffffu, acc4.w, d);
    }

    if (lane < 8) {
        __nv_bfloat16 hx = __float2bfloat16(acc4.x);
        __nv_bfloat16 hy = __float2bfloat16(acc4.y);
        __nv_bfloat16 hz = __float2bfloat16(acc4.z);
        __nv_bfloat16 hw = __float2bfloat16(acc4.w);
        __nv_bfloat162* H2 = (__nv_bfloat162*)(outh + (size_t)gwarp * DHd + c4);
        H2[0] = __nv_bfloat162(hx, hy);
        H2[1] = __nv_bfloat162(hz, hw);
        __nv_bfloat16 lx = __float2bfloat16(acc4.x - __bfloat162float(hx));
        __nv_bfloat16 ly = __float2bfloat16(acc4.y - __bfloat162float(hy));
        __nv_bfloat16 lz = __float2bfloat16(acc4.z - __bfloat162float(hz));
        __nv_bfloat16 lw = __float2bfloat16(acc4.w - __bfloat162float(hw));
        __nv_bfloat162* L2p = (__nv_bfloat162*)(outl + (size_t)gwarp * DHd + c4);
        L2p[0] = __nv_bfloat162(lx, ly);
        L2p[1] = __nv_bfloat162(lz, lw);
    }
}

// ---------------------------------------------------------------------------
extern "C" void kernel_launch(void* const* d_in, const int* in_sizes, int n_in,
                              void* d_out, int out_size)
{
    const float* query  = (const float*)d_in[0];
    const float* refpts = (const float*)d_in[1];
    const float* inp    = (const float*)d_in[2];
    const float* W_off  = (const float*)d_in[5];
    const float* b_off  = (const float*)d_in[6];
    const float* W_attn = (const float*)d_in[7];
    const float* b_attn = (const float*)d_in[8];
    const float* W_val  = (const float*)d_in[9];
    const float* b_val  = (const float*)d_in[10];
    const float* W_out  = (const float*)d_in[11];
    const float* b_out  = (const float*)d_in[12];
    float* out = (float*)d_out;

    float *p_value, *p_logits, *p_loc2, *p_att2, *p_bcat;
    __nv_bfloat16 *p_aih, *p_ail, *p_aqh, *p_aql, *p_ath, *p_atl;
    __nv_bfloat16 *p_bvh, *p_bvl, *p_bch, *p_bcl, *p_boh, *p_bol;
    cudaGetSymbolAddress((void**)&p_value,  g_value);
    cudaGetSymbolAddress((void**)&p_logits, g_logits);
    cudaGetSymbolAddress((void**)&p_loc2,   g_loc2);
    cudaGetSymbolAddress((void**)&p_att2,   g_att2);
    cudaGetSymbolAddress((void**)&p_bcat,   g_bcat);
    cudaGetSymbolAddress((void**)&p_aih, g_aih);  cudaGetSymbolAddress((void**)&p_ail, g_ail);
    cudaGetSymbolAddress((void**)&p_aqh, g_aqh);  cudaGetSymbolAddress((void**)&p_aql, g_aql);
    cudaGetSymbolAddress((void**)&p_ath, g_ath);  cudaGetSymbolAddress((void**)&p_atl, g_atl);
    cudaGetSymbolAddress((void**)&p_bvh, g_bvh);  cudaGetSymbolAddress((void**)&p_bvl, g_bvl);
    cudaGetSymbolAddress((void**)&p_bch, g_bch);  cudaGetSymbolAddress((void**)&p_bcl, g_bcl);
    cudaGetSymbolAddress((void**)&p_boh, g_boh);  cudaGetSymbolAddress((void**)&p_bol, g_bol);

    const int out_elems = NB * LQn * CC;        // 4194304
    const int locattn   = NB * LQn * MLP;       // 1048576
    bool full_out = (out_size >= out_elems + 2 * locattn);
    float* loc_out  = full_out ? (out + out_elems)           : p_loc2;
    float* attn_out = full_out ? (out + out_elems + locattn) : p_att2;

    const int smem_bytes = 2 * STAGE_B;         // 61440 (2-stage, 2 CTAs/SM)
    cudaFuncSetAttribute(gemm_mma2_kernel,
                         cudaFuncAttributeMaxDynamicSharedMemorySize, smem_bytes);

    // ---- 1) weight prep + bias concat + activation hi/lo conv (one launch) --
    {
        int n40 = NB * SSt * KK / 4;            // 1966080
        int n41 = NB * LQn * KK / 4;            // 1048576
        int convBlks = (n40 + n41 + 255) / 256;
        prepconv_kernel<<<PREP_BLKS + convBlks, 256>>>(
            W_val, W_off, W_attn, W_out, b_off, b_attn,
            p_bvh, p_bvl, p_bch, p_bcl, p_boh, p_bol, p_bcat,
            inp, p_aih, p_ail, n40, query, p_aqh, p_aql, n41);
    }
    // ---- 2) value GEMM (960 tiles) + logits GEMM (512 tiles), one launch ----
    {
        int split = (NB * SSt / 128) * 4;       // 960
        int total = split + (NB * LQn / 128) * 4;   // 1472
        gemm_mma2_kernel<<<total, 256, smem_bytes>>>(
            p_aih, p_ail, p_bvh, p_bvl, b_val,  p_value,
            p_aqh, p_aql, p_bch, p_bcl, p_bcat, p_logits,
            split);
    }
    // ---- 3) fused postproc + sampling (outputs 2&3 + bf16 A for out-GEMM) ----
    {
        int totalThreads = NB * LQn * MH * 32;
        sample_fused_kernel<<<totalThreads / 256, 256>>>(
            refpts, p_logits, loc_out, attn_out, p_ath, p_atl);
    }
    // ---- 4) out = sampled @ W_out + b_out (output 1) ----
    {
        int total = (NB * LQn / 128) * 4;       // 512
        gemm_mma2_kernel<<<total, 256, smem_bytes>>>(
            p_ath, p_atl, p_boh, p_bol, b_out, out,
            p_ath, p_atl, p_boh, p_bol, b_out, out,
            total);
    }
}